// round 13
// baseline (speedup 1.0000x reference)
#include <cuda_runtime.h>
#include <math.h>

#define B 4096
#define GRID 592              // 4 CTAs per SM (148 SMs) -> co-resident wave
#define NT 256
#define NW 8
#define FULL 0xffffffffu

// ---------------- device scratch (no allocation allowed) -------------------
__device__ float d_t0[B*14*14*32];     // pooled conv0 output, channel-last
__device__ float d_p1[B*7*7*32];       // maxpool2(h0) shortcut
__device__ float d_u1[B*7*7*32];       // binary-conv1 pooled sums (exact ints)
__device__ float d_p2[B*3*3*32];       // maxpool2(h1)
__device__ float d_u2[B*3*3*32];       // binary-conv2 pooled sums
__device__ float d_psA[3][32*GRID];    // per-stage per-block stats partials
__device__ float d_pqA[3][32*GRID];
__device__ int   d_bar[4];             // monotonic barrier counters (zero-init)

__device__ __forceinline__ float ldcg_f(const float* p) {
    float v;
    asm volatile("ld.global.cg.f32 %0, [%1];" : "=f"(v) : "l"(p));
    return v;
}

// monotonic global barrier: replay-safe, no reset needed
__device__ __forceinline__ void gbarrier(int k) {
    __syncthreads();
    if (threadIdx.x == 0) {
        __threadfence();
        int old = atomicAdd(&d_bar[k], 1);
        int target = (old / GRID + 1) * GRID;
        int v;
        do {
            asm volatile("ld.acquire.gpu.global.s32 %0, [%1];"
                         : "=r"(v) : "l"(&d_bar[k]));
        } while (v < target);
    }
    __syncthreads();
}

// ---------------- the one kernel --------------------------------------------
__global__ void __launch_bounds__(NT, 4) mega(
        const float* __restrict__ x,  const float* __restrict__ w0,
        const float* __restrict__ g0, const float* __restrict__ b0,
        const float* __restrict__ w1, const float* __restrict__ g1,
        const float* __restrict__ b1, const float* __restrict__ w2,
        const float* __restrict__ g2, const float* __restrict__ b2,
        const float* __restrict__ fw, const float* __restrict__ fb,
        float* __restrict__ out) {
    __shared__ float xs[30][32];       // zero-padded input image
    __shared__ float ws[288];          // conv0 weights
    __shared__ float ss[NW][33], sq[NW][33];
    __shared__ double dsum[NW][33], dqsum[NW][33];
    __shared__ __align__(16) unsigned X1p[16][16];   // padded sign bitmap (14x14)
    __shared__ __align__(16) unsigned X2p[9][9];     // padded sign bitmap (7x7)
    __shared__ unsigned Wb1[288], Wb2[288];
    __shared__ float h1s[49][32];
    __shared__ float bnS[3][32], bnB[3][32];

    const int t = threadIdx.x, lane = t & 31, w = t >> 5, blk = blockIdx.x;

    // ---- init: zero padded bitmaps (borders stay 0), load/pack weights ----
    ((unsigned*)X1p)[t] = 0u;          // 256 words exactly
    if (t < 81) ((unsigned*)X2p)[t] = 0u;
    for (int i = t; i < 288; i += NT) ws[i] = w0[i];   // FIXED: full coverage
    for (int task = w; task < 576; task += NW) {       // lane = input channel
        const float* wsrc = (task < 288) ? w1 : w2;
        int r = (task < 288) ? task : task - 288;
        int o = r / 9, tap = r % 9;
        unsigned bal = __ballot_sync(FULL, wsrc[o*288 + lane*9 + tap] > 0.f);
        if (lane == 0) ((task < 288) ? Wb1 : Wb2)[r] = bal;
    }
    __syncthreads();

    // =================== P1: conv0 (Cin=1, pad=1) + 2x2 pool + stats ========
    {
        float wr[9];
#pragma unroll
        for (int k = 0; k < 9; k++) wr[k] = ws[lane*9 + k];
        float s1 = 0.f, q1 = 0.f;
        for (int img = blk; img < B; img += GRID) {
            __syncthreads();           // previous image's compute done
            const float* xb = x + img*784;
            for (int i = t; i < 784; i += NT) {
                int r = i / 28;
                xs[r + 1][i - r*28 + 1] = xb[i];
            }
            __syncthreads();
            for (int py = w; py < 14; py += NW) {
                float* outp = d_t0 + ((long)img*196 + py*14)*32 + lane;
#pragma unroll
                for (int j2 = 0; j2 < 7; j2++) {
                    float xv[4][6];
#pragma unroll
                    for (int r = 0; r < 4; r++)
#pragma unroll
                        for (int cc = 0; cc < 6; cc++)
                            xv[r][cc] = xs[2*py + r][4*j2 + cc];
#pragma unroll
                    for (int half = 0; half < 2; half++) {
                        float m = -INFINITY;
#pragma unroll
                        for (int dy = 0; dy < 2; dy++)
#pragma unroll
                            for (int dx = 0; dx < 2; dx++) {
                                float acc = 0.f;
#pragma unroll
                                for (int ky = 0; ky < 3; ky++)
#pragma unroll
                                    for (int kx = 0; kx < 3; kx++)
                                        acc = fmaf(wr[ky*3+kx],
                                                   xv[dy+ky][2*half+dx+kx], acc);
                                m = fmaxf(m, acc);
                            }
                        outp[(2*j2 + half)*32] = m;
                        s1 += m; q1 = fmaf(m, m, q1);
                    }
                }
            }
        }
        __syncthreads();
        ss[w][lane] = s1; sq[w][lane] = q1;
        __syncthreads();
        if (t < 32) {
            float ts = 0.f, tq = 0.f;
#pragma unroll
            for (int j = 0; j < NW; j++) { ts += ss[j][t]; tq += sq[j][t]; }
            d_psA[0][t*GRID + blk] = ts;
            d_pqA[0][t*GRID + blk] = tq;
        }
    }
    gbarrier(0);
    // finalize BN0 (all blocks redundantly; warp-parallel partial reduce)
    {
        float fs = 0.f, fq = 0.f;
        for (int i = w; i < GRID; i += NW) {
            fs += ldcg_f(&d_psA[0][lane*GRID + i]);
            fq += ldcg_f(&d_pqA[0][lane*GRID + i]);
        }
        dsum[w][lane] = (double)fs; dqsum[w][lane] = (double)fq;
        __syncthreads();
        if (t < 32) {
            double s = 0.0, q = 0.0;
#pragma unroll
            for (int j = 0; j < NW; j++) { s += dsum[j][t]; q += dqsum[j][t]; }
            double n = (double)B * 196.0;
            double mean = s / n, var = q / n - mean * mean;
            double sc = (double)g0[t] / sqrt(var + 1e-5);
            bnS[0][t] = (float)sc;
            bnB[0][t] = (float)((double)b0[t] - mean * sc);
        }
        __syncthreads();
    }

    // =================== P2: pack X1 + p1 + binary conv1 + pool + stats =====
    {
        unsigned wb[9]; int Kc0, Kc2, Kc6, Kc8, Kt, Kb, Kl, Kr;
        {
            int Kc[9];
#pragma unroll
            for (int k = 0; k < 9; k++) { wb[k] = Wb1[lane*9 + k]; Kc[k] = 32 - 2*__popc(wb[k]); }
            Kt = Kc[0]+Kc[1]+Kc[2]; Kb = Kc[6]+Kc[7]+Kc[8];
            Kl = Kc[0]+Kc[3]+Kc[6]; Kr = Kc[2]+Kc[5]+Kc[8];
            Kc0 = Kc[0]; Kc2 = Kc[2]; Kc6 = Kc[6]; Kc8 = Kc[8];
        }
        float sc = bnS[0][lane], bs = bnB[0][lane];
        float s2 = 0.f, q2 = 0.f;
        for (int img = blk; img < B; img += GRID) {
            for (int j = w; j < 49; j += NW) {
                int pyy = j / 7, pxx = j % 7;
                float hmax = -INFINITY;
                unsigned myw = 0;
#pragma unroll
                for (int d = 0; d < 4; d++) {
                    int y = 2*pyy + (d >> 1), xx = 2*pxx + (d & 1);
                    float v = d_t0[((long)img*196 + y*14 + xx)*32 + lane];
                    float h = fmaf(sc, v, bs);
                    unsigned bal = __ballot_sync(FULL, h > 0.f);
                    if (lane == d) myw = bal;
                    hmax = fmaxf(hmax, h);
                }
                if (lane < 4) X1p[2*pyy + (lane>>1) + 1][2*pxx + (lane&1) + 1] = myw;
                d_p1[(img*49 + j)*32 + lane] = hmax;
            }
            __syncthreads();
            for (int j = w; j < 49; j += NW) {
                int pyy = j / 7, pxx = j % 7;
                unsigned xw[4][4];
#pragma unroll
                for (int r4 = 0; r4 < 4; r4++) {
                    const uint2* Xr = reinterpret_cast<const uint2*>(&X1p[2*pyy + r4][2*pxx]);
                    uint2 lo = Xr[0], hi = Xr[1];
                    xw[r4][0] = lo.x; xw[r4][1] = lo.y; xw[r4][2] = hi.x; xw[r4][3] = hi.y;
                }
                int vv[4];
#pragma unroll
                for (int dy = 0; dy < 2; dy++)
#pragma unroll
                    for (int dx = 0; dx < 2; dx++) {
                        int sump = 0;
#pragma unroll
                        for (int ky = 0; ky < 3; ky++)
#pragma unroll
                            for (int kx = 0; kx < 3; kx++)
                                sump += __popc(xw[dy+ky][dx+kx] ^ wb[ky*3+kx]);
                        vv[dy*2+dx] = 288 - 2*sump;
                    }
                if (pyy == 0 || pyy == 6 || pxx == 0 || pxx == 6) {
#pragma unroll
                    for (int dy = 0; dy < 2; dy++)
#pragma unroll
                        for (int dx = 0; dx < 2; dx++) {
                            bool top = (pyy == 0) && (dy == 0);
                            bool bot = (pyy == 6) && (dy == 1);
                            bool lef = (pxx == 0) && (dx == 0);
                            bool rig = (pxx == 6) && (dx == 1);
                            int corr = 0;
                            if (top) corr += Kt;
                            if (bot) corr += Kb;
                            if (lef) corr += Kl;
                            if (rig) corr += Kr;
                            if (top && lef) corr -= Kc0;
                            if (top && rig) corr -= Kc2;
                            if (bot && lef) corr -= Kc6;
                            if (bot && rig) corr -= Kc8;
                            vv[dy*2+dx] -= corr;
                        }
                }
                int m = max(max(vv[0], vv[1]), max(vv[2], vv[3]));
                float fm = (float)m;
                d_u1[(img*49 + j)*32 + lane] = fm;
                s2 += fm; q2 = fmaf(fm, fm, q2);
            }
            __syncthreads();           // X1p reusable for next image
        }
        __syncthreads();
        ss[w][lane] = s2; sq[w][lane] = q2;
        __syncthreads();
        if (t < 32) {
            float ts = 0.f, tq = 0.f;
#pragma unroll
            for (int j = 0; j < NW; j++) { ts += ss[j][t]; tq += sq[j][t]; }
            d_psA[1][t*GRID + blk] = ts;
            d_pqA[1][t*GRID + blk] = tq;
        }
    }
    gbarrier(1);
    {
        float fs = 0.f, fq = 0.f;
        for (int i = w; i < GRID; i += NW) {
            fs += ldcg_f(&d_psA[1][lane*GRID + i]);
            fq += ldcg_f(&d_pqA[1][lane*GRID + i]);
        }
        dsum[w][lane] = (double)fs; dqsum[w][lane] = (double)fq;
        __syncthreads();
        if (t < 32) {
            double s = 0.0, q = 0.0;
#pragma unroll
            for (int j = 0; j < NW; j++) { s += dsum[j][t]; q += dqsum[j][t]; }
            double n = (double)B * 49.0;
            double mean = s / n, var = q / n - mean * mean;
            double sc = (double)g1[t] / sqrt(var + 1e-5);
            bnS[1][t] = (float)sc;
            bnB[1][t] = (float)((double)b1[t] - mean * sc);
        }
        __syncthreads();
    }

    // =================== P3: h1 + X2 + p2 + binary conv2 + stats ============
    {
        unsigned wb[9];
#pragma unroll
        for (int k = 0; k < 9; k++) wb[k] = Wb2[lane*9 + k];
        int Kc0 = 32 - 2*__popc(wb[0]);
        int Kc1 = 32 - 2*__popc(wb[1]);
        int Kc2 = 32 - 2*__popc(wb[2]);
        int Kc3 = 32 - 2*__popc(wb[3]);
        int Kc6 = 32 - 2*__popc(wb[6]);
        int Kt = Kc0 + Kc1 + Kc2, Kl = Kc0 + Kc3 + Kc6;
        float sc = bnS[1][lane], bs = bnB[1][lane];
        float s3 = 0.f, q3 = 0.f;
        for (int img = blk; img < B; img += GRID) {
            for (int j = w; j < 49; j += NW) {
                float hv = fmaf(sc, d_u1[(img*49 + j)*32 + lane], bs)
                         + d_p1[(img*49 + j)*32 + lane];
                h1s[j][lane] = hv;
                unsigned bal = __ballot_sync(FULL, hv > 0.f);
                if (lane == 0) X2p[j/7 + 1][j%7 + 1] = bal;
            }
            __syncthreads();
            for (int j = w; j < 9; j += NW) {
                int pyy = j / 3, pxx = j % 3;
                int i0 = (2*pyy)*7 + 2*pxx;
                float m = fmaxf(fmaxf(h1s[i0][lane],   h1s[i0+1][lane]),
                                fmaxf(h1s[i0+7][lane], h1s[i0+8][lane]));
                d_p2[(img*9 + j)*32 + lane] = m;
                unsigned xw[4][4];
#pragma unroll
                for (int r4 = 0; r4 < 4; r4++)
#pragma unroll
                    for (int c4 = 0; c4 < 4; c4++)
                        xw[r4][c4] = X2p[2*pyy + r4][2*pxx + c4];
                int mm = -100000;
#pragma unroll
                for (int dy = 0; dy < 2; dy++)
#pragma unroll
                    for (int dx = 0; dx < 2; dx++) {
                        int sump = 0;
#pragma unroll
                        for (int ky = 0; ky < 3; ky++)
#pragma unroll
                            for (int kx = 0; kx < 3; kx++)
                                sump += __popc(xw[dy+ky][dx+kx] ^ wb[ky*3+kx]);
                        int v = 288 - 2*sump;
                        bool top = (pyy == 0) && (dy == 0);
                        bool lef = (pxx == 0) && (dx == 0);
                        int corr = 0;
                        if (top) corr += Kt;
                        if (lef) corr += Kl;
                        if (top && lef) corr -= Kc0;
                        mm = max(mm, v - corr);
                    }
                float fm = (float)mm;
                d_u2[(img*9 + j)*32 + lane] = fm;
                s3 += fm; q3 = fmaf(fm, fm, q3);
            }
            __syncthreads();
        }
        __syncthreads();
        ss[w][lane] = s3; sq[w][lane] = q3;
        __syncthreads();
        if (t < 32) {
            float ts = 0.f, tq = 0.f;
#pragma unroll
            for (int j = 0; j < NW; j++) { ts += ss[j][t]; tq += sq[j][t]; }
            d_psA[2][t*GRID + blk] = ts;
            d_pqA[2][t*GRID + blk] = tq;
        }
    }
    gbarrier(2);
    {
        float fs = 0.f, fq = 0.f;
        for (int i = w; i < GRID; i += NW) {
            fs += ldcg_f(&d_psA[2][lane*GRID + i]);
            fq += ldcg_f(&d_pqA[2][lane*GRID + i]);
        }
        dsum[w][lane] = (double)fs; dqsum[w][lane] = (double)fq;
        __syncthreads();
        if (t < 32) {
            double s = 0.0, q = 0.0;
#pragma unroll
            for (int j = 0; j < NW; j++) { s += dsum[j][t]; q += dqsum[j][t]; }
            double n = (double)B * 9.0;
            double mean = s / n, var = q / n - mean * mean;
            double sc = (double)g2[t] / sqrt(var + 1e-5);
            bnS[2][t] = (float)sc;
            bnB[2][t] = (float)((double)b2[t] - mean * sc);
        }
        __syncthreads();
    }

    // =================== P4: fused h2 = bn(u2)+p2, flatten, FC ==============
    {
        float sc = bnS[2][lane], bs = bnB[2][lane];
        int b = blk*NW + w;            // GRID*NW = 4736 >= B: at most one image/warp
        if (b < B) {
            float acc[10];
#pragma unroll
            for (int k = 0; k < 10; k++) acc[k] = 0.f;
#pragma unroll
            for (int ij = 0; ij < 9; ij++) {
                float h = fmaf(sc, ldcg_f(&d_u2[(b*9 + ij)*32 + lane]), bs)
                        + ldcg_f(&d_p2[(b*9 + ij)*32 + lane]);
#pragma unroll
                for (int k = 0; k < 10; k++)
                    acc[k] = fmaf(h, fw[k*288 + lane*9 + ij], acc[k]);
            }
#pragma unroll
            for (int k = 0; k < 10; k++) {
#pragma unroll
                for (int off = 16; off; off >>= 1)
                    acc[k] += __shfl_xor_sync(FULL, acc[k], off);
                if (lane == k) out[b*10 + k] = acc[k] + fb[k];
            }
        }
    }
}

// ---------------- launch -----------------------------------------------------
extern "C" void kernel_launch(void* const* d_in, const int* in_sizes, int n_in,
                              void* d_out, int out_size) {
    const float* x  = (const float*)d_in[0];
    const float* w0 = (const float*)d_in[1];
    const float* g0 = (const float*)d_in[2];
    const float* b0 = (const float*)d_in[3];
    const float* w1 = (const float*)d_in[4];
    const float* g1 = (const float*)d_in[5];
    const float* b1 = (const float*)d_in[6];
    const float* w2 = (const float*)d_in[7];
    const float* g2 = (const float*)d_in[8];
    const float* b2 = (const float*)d_in[9];
    const float* fw = (const float*)d_in[10];
    const float* fb = (const float*)d_in[11];
    float* out = (float*)d_out;

    mega<<<GRID, NT>>>(x, w0, g0, b0, w1, g1, b1, w2, g2, b2, fw, fb, out);
}

// round 14
// speedup vs baseline: 2.8351x; 2.8351x over previous
#include <cuda_runtime.h>
#include <math.h>

#define B 4096
#define GRID 592              // 4 CTAs per SM (148 SMs) -> co-resident wave
#define NT 256
#define NW 8
#define FULL 0xffffffffu

// ---------------- device scratch (no allocation allowed) -------------------
__device__ float d_t0[B*14*14*32];     // pooled conv0 output, channel-last
__device__ float d_p1[B*7*7*32];       // maxpool2(h0) shortcut
__device__ float d_u1[B*7*7*32];       // binary-conv1 pooled sums (exact ints)
__device__ float d_p2[B*3*3*32];       // maxpool2(h1)
__device__ float d_u2[B*3*3*32];       // binary-conv2 pooled sums
__device__ float d_psA[3][GRID*32];    // stats partials, COALESCED: [blk][ch]
__device__ float d_pqA[3][GRID*32];
__device__ int   d_bar[4];             // monotonic barrier counters (zero-init)

__device__ __forceinline__ float ldcg_f(const float* p) {
    float v;
    asm volatile("ld.global.cg.f32 %0, [%1];" : "=f"(v) : "l"(p));
    return v;
}

// monotonic global barrier: replay-safe, no reset needed
__device__ __forceinline__ void gbarrier(int k) {
    __syncthreads();
    if (threadIdx.x == 0) {
        __threadfence();
        int old = atomicAdd(&d_bar[k], 1);
        int target = (old / GRID + 1) * GRID;
        int v;
        do {
            asm volatile("ld.acquire.gpu.global.s32 %0, [%1];"
                         : "=r"(v) : "l"(&d_bar[k]));
        } while (v < target);
    }
    __syncthreads();
}

// ---------------- the one kernel --------------------------------------------
__global__ void __launch_bounds__(NT, 4) mega(
        const float* __restrict__ x,  const float* __restrict__ w0,
        const float* __restrict__ g0, const float* __restrict__ b0,
        const float* __restrict__ w1, const float* __restrict__ g1,
        const float* __restrict__ b1, const float* __restrict__ w2,
        const float* __restrict__ g2, const float* __restrict__ b2,
        const float* __restrict__ fw, const float* __restrict__ fb,
        float* __restrict__ out) {
    __shared__ __align__(16) float xs[30][32];       // zero-padded input image
    __shared__ float ws[288];          // conv0 weights
    __shared__ float ss[NW][33], sq[NW][33];
    __shared__ double dsum[NW][33], dqsum[NW][33];
    __shared__ __align__(16) unsigned X1p[16][16];   // padded sign bitmap (14x14)
    __shared__ __align__(16) unsigned X2p[9][9];     // padded sign bitmap (7x7)
    __shared__ unsigned Wb1[288], Wb2[288];
    __shared__ float h1s[49][32];
    __shared__ float bnS[3][32], bnB[3][32];

    const int t = threadIdx.x, lane = t & 31, w = t >> 5, blk = blockIdx.x;

    // ---- init: zero padded bitmaps (borders stay 0), load/pack weights ----
    ((unsigned*)X1p)[t] = 0u;          // 256 words exactly
    if (t < 81) ((unsigned*)X2p)[t] = 0u;
    for (int i = t; i < 288; i += NT) ws[i] = w0[i];
    for (int task = w; task < 576; task += NW) {     // lane = input channel
        const float* wsrc = (task < 288) ? w1 : w2;
        int r = (task < 288) ? task : task - 288;
        int o = r / 9, tap = r % 9;
        unsigned bal = __ballot_sync(FULL, wsrc[o*288 + lane*9 + tap] > 0.f);
        if (lane == 0) ((task < 288) ? Wb1 : Wb2)[r] = bal;
    }
    __syncthreads();

    // =================== P1: conv0 (Cin=1, pad=1) + 2x2 pool + stats ========
    {
        float wr[9];
#pragma unroll
        for (int k = 0; k < 9; k++) wr[k] = ws[lane*9 + k];
        float s1 = 0.f, q1 = 0.f;
        for (int img = blk; img < B; img += GRID) {
            __syncthreads();           // previous image's compute done
            const float* xb = x + img*784;
            for (int i = t; i < 784; i += NT) {
                int r = i / 28;
                xs[r + 1][i - r*28 + 1] = xb[i];
            }
            __syncthreads();
            for (int py = w; py < 14; py += NW) {
                float* outp = d_t0 + (img*196 + py*14)*32 + lane;
#pragma unroll
                for (int j2 = 0; j2 < 7; j2++) {
                    // 6 columns x 4 rows via vector LDS (aligned)
                    float xv[4][6];
#pragma unroll
                    for (int r = 0; r < 4; r++) {
                        float4 a = *reinterpret_cast<const float4*>(&xs[2*py + r][4*j2]);
                        float2 bb = *reinterpret_cast<const float2*>(&xs[2*py + r][4*j2 + 4]);
                        xv[r][0] = a.x; xv[r][1] = a.y; xv[r][2] = a.z;
                        xv[r][3] = a.w; xv[r][4] = bb.x; xv[r][5] = bb.y;
                    }
#pragma unroll
                    for (int half = 0; half < 2; half++) {
                        float acc[4];
#pragma unroll
                        for (int dy = 0; dy < 2; dy++)
#pragma unroll
                            for (int dx = 0; dx < 2; dx++) {
                                float a = 0.f;
#pragma unroll
                                for (int ky = 0; ky < 3; ky++)
#pragma unroll
                                    for (int kx = 0; kx < 3; kx++)
                                        a = fmaf(wr[ky*3+kx],
                                                 xv[dy+ky][2*half+dx+kx], a);
                                acc[dy*2+dx] = a;
                            }
                        float m = fmaxf(fmaxf(acc[0], acc[1]), fmaxf(acc[2], acc[3]));
                        outp[0] = m;
                        outp += 32;
                        s1 += m; q1 = fmaf(m, m, q1);
                    }
                }
            }
        }
        __syncthreads();
        ss[w][lane] = s1; sq[w][lane] = q1;
        __syncthreads();
        if (t < 32) {
            float ts = 0.f, tq = 0.f;
#pragma unroll
            for (int j = 0; j < NW; j++) { ts += ss[j][t]; tq += sq[j][t]; }
            d_psA[0][blk*32 + t] = ts;     // coalesced [blk][ch]
            d_pqA[0][blk*32 + t] = tq;
        }
    }
    gbarrier(0);
    // finalize BN0 (all blocks redundantly; fully coalesced 128B rows)
    {
        float fs = 0.f, fq = 0.f;
        for (int i = w; i < GRID; i += NW) {
            fs += ldcg_f(&d_psA[0][i*32 + lane]);
            fq += ldcg_f(&d_pqA[0][i*32 + lane]);
        }
        dsum[w][lane] = (double)fs; dqsum[w][lane] = (double)fq;
        __syncthreads();
        if (t < 32) {
            double s = 0.0, q = 0.0;
#pragma unroll
            for (int j = 0; j < NW; j++) { s += dsum[j][t]; q += dqsum[j][t]; }
            double n = (double)B * 196.0;
            double mean = s / n, var = q / n - mean * mean;
            double sc = (double)g0[t] / sqrt(var + 1e-5);
            bnS[0][t] = (float)sc;
            bnB[0][t] = (float)((double)b0[t] - mean * sc);
        }
        __syncthreads();
    }

    // =================== P2: pack X1 + p1 + binary conv1 + pool + stats =====
    {
        unsigned wb[9]; int Kc0, Kc2, Kc6, Kc8, Kt, Kb, Kl, Kr;
        {
            int Kc[9];
#pragma unroll
            for (int k = 0; k < 9; k++) { wb[k] = Wb1[lane*9 + k]; Kc[k] = 32 - 2*__popc(wb[k]); }
            Kt = Kc[0]+Kc[1]+Kc[2]; Kb = Kc[6]+Kc[7]+Kc[8];
            Kl = Kc[0]+Kc[3]+Kc[6]; Kr = Kc[2]+Kc[5]+Kc[8];
            Kc0 = Kc[0]; Kc2 = Kc[2]; Kc6 = Kc[6]; Kc8 = Kc[8];
        }
        float sc = bnS[0][lane], bs = bnB[0][lane];
        const int py0 = w / 7, px0 = w - 7*py0;        // warp's first pixel
        float s2 = 0.f, q2 = 0.f;
        for (int img = blk; img < B; img += GRID) {
            const float* t0b = d_t0 + img*196*32 + lane;
            float* p1b = d_p1 + (img*49 + w)*32 + lane;
            {
                int py = py0, px = px0;
                for (int j = w; j < 49; j += NW) {
                    const float* q4 = t0b + (py*28 + 2*px)*32;   // y=2py, x=2px
                    float v0 = q4[0],      v1 = q4[32];
                    float v2 = q4[14*32],  v3 = q4[15*32];
                    float h0 = fmaf(sc, v0, bs), h1 = fmaf(sc, v1, bs);
                    float h2 = fmaf(sc, v2, bs), h3 = fmaf(sc, v3, bs);
                    unsigned b0_ = __ballot_sync(FULL, h0 > 0.f);
                    unsigned b1_ = __ballot_sync(FULL, h1 > 0.f);
                    unsigned b2_ = __ballot_sync(FULL, h2 > 0.f);
                    unsigned b3_ = __ballot_sync(FULL, h3 > 0.f);
                    unsigned myw = (lane == 0) ? b0_ : (lane == 1) ? b1_
                                 : (lane == 2) ? b2_ : b3_;
                    if (lane < 4)
                        X1p[2*py + (lane>>1) + 1][2*px + (lane&1) + 1] = myw;
                    float hmax = fmaxf(fmaxf(h0, h1), fmaxf(h2, h3));
                    p1b[0] = hmax;
                    p1b += NW*32;
                    s2 += hmax;        // note: stats are over u1, added below
                    s2 -= hmax;        // (keep structure; optimizer removes)
                    px += 1; py += 1;  // j += 8 == +7 +1
                    if (px >= 7) { px -= 7; py += 1; }
                }
            }
            __syncthreads();
            {
                int py = py0, px = px0;
                float* u1b = d_u1 + (img*49 + w)*32 + lane;
                for (int j = w; j < 49; j += NW) {
                    unsigned xw[4][4];
#pragma unroll
                    for (int r4 = 0; r4 < 4; r4++) {
                        const uint2* Xr = reinterpret_cast<const uint2*>(&X1p[2*py + r4][2*px]);
                        uint2 lo = Xr[0], hi = Xr[1];
                        xw[r4][0] = lo.x; xw[r4][1] = lo.y; xw[r4][2] = hi.x; xw[r4][3] = hi.y;
                    }
                    int vv[4];
#pragma unroll
                    for (int dy = 0; dy < 2; dy++)
#pragma unroll
                        for (int dx = 0; dx < 2; dx++) {
                            int sump = 0;
#pragma unroll
                            for (int ky = 0; ky < 3; ky++)
#pragma unroll
                                for (int kx = 0; kx < 3; kx++)
                                    sump += __popc(xw[dy+ky][dx+kx] ^ wb[ky*3+kx]);
                            vv[dy*2+dx] = 288 - 2*sump;
                        }
                    if (py == 0 || py == 6 || px == 0 || px == 6) {
#pragma unroll
                        for (int dy = 0; dy < 2; dy++)
#pragma unroll
                            for (int dx = 0; dx < 2; dx++) {
                                bool top = (py == 0) && (dy == 0);
                                bool bot = (py == 6) && (dy == 1);
                                bool lef = (px == 0) && (dx == 0);
                                bool rig = (px == 6) && (dx == 1);
                                int corr = 0;
                                if (top) corr += Kt;
                                if (bot) corr += Kb;
                                if (lef) corr += Kl;
                                if (rig) corr += Kr;
                                if (top && lef) corr -= Kc0;
                                if (top && rig) corr -= Kc2;
                                if (bot && lef) corr -= Kc6;
                                if (bot && rig) corr -= Kc8;
                                vv[dy*2+dx] -= corr;
                            }
                    }
                    int m = max(max(vv[0], vv[1]), max(vv[2], vv[3]));
                    float fm = (float)m;
                    u1b[0] = fm;
                    u1b += NW*32;
                    s2 += fm; q2 = fmaf(fm, fm, q2);
                    px += 1; py += 1;
                    if (px >= 7) { px -= 7; py += 1; }
                }
            }
            __syncthreads();           // X1p reusable for next image
        }
        __syncthreads();
        ss[w][lane] = s2; sq[w][lane] = q2;
        __syncthreads();
        if (t < 32) {
            float ts = 0.f, tq = 0.f;
#pragma unroll
            for (int j = 0; j < NW; j++) { ts += ss[j][t]; tq += sq[j][t]; }
            d_psA[1][blk*32 + t] = ts;
            d_pqA[1][blk*32 + t] = tq;
        }
    }
    gbarrier(1);
    {
        float fs = 0.f, fq = 0.f;
        for (int i = w; i < GRID; i += NW) {
            fs += ldcg_f(&d_psA[1][i*32 + lane]);
            fq += ldcg_f(&d_pqA[1][i*32 + lane]);
        }
        dsum[w][lane] = (double)fs; dqsum[w][lane] = (double)fq;
        __syncthreads();
        if (t < 32) {
            double s = 0.0, q = 0.0;
#pragma unroll
            for (int j = 0; j < NW; j++) { s += dsum[j][t]; q += dqsum[j][t]; }
            double n = (double)B * 49.0;
            double mean = s / n, var = q / n - mean * mean;
            double sc = (double)g1[t] / sqrt(var + 1e-5);
            bnS[1][t] = (float)sc;
            bnB[1][t] = (float)((double)b1[t] - mean * sc);
        }
        __syncthreads();
    }

    // =================== P3: h1 + X2 + p2 + binary conv2 + stats ============
    {
        unsigned wb[9];
#pragma unroll
        for (int k = 0; k < 9; k++) wb[k] = Wb2[lane*9 + k];
        int Kc0 = 32 - 2*__popc(wb[0]);
        int Kc1 = 32 - 2*__popc(wb[1]);
        int Kc2 = 32 - 2*__popc(wb[2]);
        int Kc3 = 32 - 2*__popc(wb[3]);
        int Kc6 = 32 - 2*__popc(wb[6]);
        int Kt = Kc0 + Kc1 + Kc2, Kl = Kc0 + Kc3 + Kc6;
        float sc = bnS[1][lane], bs = bnB[1][lane];
        float s3 = 0.f, q3 = 0.f;
        for (int img = blk; img < B; img += GRID) {
            const float* u1b = d_u1 + (img*49 + w)*32 + lane;
            const float* p1b = d_p1 + (img*49 + w)*32 + lane;
            for (int j = w; j < 49; j += NW) {
                float hv = fmaf(sc, u1b[0], bs) + p1b[0];
                u1b += NW*32; p1b += NW*32;
                h1s[j][lane] = hv;
                unsigned bal = __ballot_sync(FULL, hv > 0.f);
                if (lane == 0) X2p[j/7 + 1][j%7 + 1] = bal;
            }
            __syncthreads();
            if (w < 9) {               // warp w -> one 3x3 output pixel (wait: 9 pixels, 8 warps)
                // handled below via loop to cover j = w and w+8
            }
            for (int j = w; j < 9; j += NW) {
                int pyy = (j >= 6) ? 2 : (j >= 3 ? 1 : 0);
                int pxx = j - 3*pyy;
                int i0 = (2*pyy)*7 + 2*pxx;
                float m = fmaxf(fmaxf(h1s[i0][lane],   h1s[i0+1][lane]),
                                fmaxf(h1s[i0+7][lane], h1s[i0+8][lane]));
                d_p2[(img*9 + j)*32 + lane] = m;
                unsigned xw[4][4];
#pragma unroll
                for (int r4 = 0; r4 < 4; r4++)
#pragma unroll
                    for (int c4 = 0; c4 < 4; c4++)
                        xw[r4][c4] = X2p[2*pyy + r4][2*pxx + c4];
                int mm = -100000;
#pragma unroll
                for (int dy = 0; dy < 2; dy++)
#pragma unroll
                    for (int dx = 0; dx < 2; dx++) {
                        int sump = 0;
#pragma unroll
                        for (int ky = 0; ky < 3; ky++)
#pragma unroll
                            for (int kx = 0; kx < 3; kx++)
                                sump += __popc(xw[dy+ky][dx+kx] ^ wb[ky*3+kx]);
                        int v = 288 - 2*sump;
                        bool top = (pyy == 0) && (dy == 0);
                        bool lef = (pxx == 0) && (dx == 0);
                        int corr = 0;
                        if (top) corr += Kt;
                        if (lef) corr += Kl;
                        if (top && lef) corr -= Kc0;
                        mm = max(mm, v - corr);
                    }
                float fm = (float)mm;
                d_u2[(img*9 + j)*32 + lane] = fm;
                s3 += fm; q3 = fmaf(fm, fm, q3);
            }
            __syncthreads();
        }
        __syncthreads();
        ss[w][lane] = s3; sq[w][lane] = q3;
        __syncthreads();
        if (t < 32) {
            float ts = 0.f, tq = 0.f;
#pragma unroll
            for (int j = 0; j < NW; j++) { ts += ss[j][t]; tq += sq[j][t]; }
            d_psA[2][blk*32 + t] = ts;
            d_pqA[2][blk*32 + t] = tq;
        }
    }
    gbarrier(2);
    {
        float fs = 0.f, fq = 0.f;
        for (int i = w; i < GRID; i += NW) {
            fs += ldcg_f(&d_psA[2][i*32 + lane]);
            fq += ldcg_f(&d_pqA[2][i*32 + lane]);
        }
        dsum[w][lane] = (double)fs; dqsum[w][lane] = (double)fq;
        __syncthreads();
        if (t < 32) {
            double s = 0.0, q = 0.0;
#pragma unroll
            for (int j = 0; j < NW; j++) { s += dsum[j][t]; q += dqsum[j][t]; }
            double n = (double)B * 9.0;
            double mean = s / n, var = q / n - mean * mean;
            double sc = (double)g2[t] / sqrt(var + 1e-5);
            bnS[2][t] = (float)sc;
            bnB[2][t] = (float)((double)b2[t] - mean * sc);
        }
        __syncthreads();
    }

    // =================== P4: fused h2 = bn(u2)+p2, flatten, FC ==============
    {
        float sc = bnS[2][lane], bs = bnB[2][lane];
        int b = blk*NW + w;            // GRID*NW = 4736 >= B: at most one image/warp
        if (b < B) {
            float acc[10];
#pragma unroll
            for (int k = 0; k < 10; k++) acc[k] = 0.f;
#pragma unroll
            for (int ij = 0; ij < 9; ij++) {
                float h = fmaf(sc, ldcg_f(&d_u2[(b*9 + ij)*32 + lane]), bs)
                        + ldcg_f(&d_p2[(b*9 + ij)*32 + lane]);
#pragma unroll
                for (int k = 0; k < 10; k++)
                    acc[k] = fmaf(h, fw[k*288 + lane*9 + ij], acc[k]);
            }
#pragma unroll
            for (int k = 0; k < 10; k++) {
#pragma unroll
                for (int off = 16; off; off >>= 1)
                    acc[k] += __shfl_xor_sync(FULL, acc[k], off);
                if (lane == k) out[b*10 + k] = acc[k] + fb[k];
            }
        }
    }
}

// ---------------- launch -----------------------------------------------------
extern "C" void kernel_launch(void* const* d_in, const int* in_sizes, int n_in,
                              void* d_out, int out_size) {
    const float* x  = (const float*)d_in[0];
    const float* w0 = (const float*)d_in[1];
    const float* g0 = (const float*)d_in[2];
    const float* b0 = (const float*)d_in[3];
    const float* w1 = (const float*)d_in[4];
    const float* g1 = (const float*)d_in[5];
    const float* b1 = (const float*)d_in[6];
    const float* w2 = (const float*)d_in[7];
    const float* g2 = (const float*)d_in[8];
    const float* b2 = (const float*)d_in[9];
    const float* fw = (const float*)d_in[10];
    const float* fb = (const float*)d_in[11];
    float* out = (float*)d_out;

    mega<<<GRID, NT>>>(x, w0, g0, b0, w1, g1, b1, w2, g2, b2, fw, fb, out);
}

// round 16
// speedup vs baseline: 2.9433x; 1.0382x over previous
#include <cuda_runtime.h>
#include <math.h>

#define B 4096
#define GRID 740              // 5 CTAs per SM (148 SMs) -> co-resident wave
#define NT 256
#define NW 8
#define FULL 0xffffffffu

// ---------------- device scratch (no allocation allowed) -------------------
__device__ float d_t0[B*14*14*32];     // pooled conv0 output, channel-last
__device__ float d_p1[B*7*7*32];       // maxpool2(h0) shortcut
__device__ float d_u1[B*7*7*32];       // binary-conv1 pooled sums (exact ints)
__device__ float d_p2[B*3*3*32];       // maxpool2(h1)
__device__ float d_u2[B*3*3*32];       // binary-conv2 pooled sums
__device__ float d_psA[3][GRID*32];    // stats partials, coalesced: [blk][ch]
__device__ float d_pqA[3][GRID*32];
__device__ int   d_bar[4];             // monotonic barrier counters (zero-init)

__device__ __forceinline__ float ldcg_f(const float* p) {
    float v;
    asm volatile("ld.global.cg.f32 %0, [%1];" : "=f"(v) : "l"(p));
    return v;
}

// monotonic global barrier: replay-safe, no reset needed
__device__ __forceinline__ void gbarrier(int k) {
    __syncthreads();
    if (threadIdx.x == 0) {
        __threadfence();
        int old = atomicAdd(&d_bar[k], 1);
        int target = (old / GRID + 1) * GRID;
        int v;
        do {
            asm volatile("ld.acquire.gpu.global.s32 %0, [%1];"
                         : "=r"(v) : "l"(&d_bar[k]));
        } while (v < target);
    }
    __syncthreads();
}

// ---------------- the one kernel --------------------------------------------
__global__ void __launch_bounds__(NT, 5) mega(
        const float* __restrict__ x,  const float* __restrict__ w0,
        const float* __restrict__ g0, const float* __restrict__ b0,
        const float* __restrict__ w1, const float* __restrict__ g1,
        const float* __restrict__ b1, const float* __restrict__ w2,
        const float* __restrict__ g2, const float* __restrict__ b2,
        const float* __restrict__ fw, const float* __restrict__ fb,
        float* __restrict__ out) {
    __shared__ __align__(16) float xs[30][32];       // zero-padded input image
    __shared__ float ws[288];          // conv0 weights
    __shared__ float ss[NW][33], sq[NW][33];
    __shared__ double dsum[NW][33], dqsum[NW][33];
    __shared__ __align__(16) unsigned X1p[16][16];   // padded sign bitmap (14x14)
    __shared__ __align__(16) unsigned X2p[9][9];     // padded sign bitmap (7x7)
    __shared__ unsigned Wb1[288], Wb2[288];
    __shared__ float h1s[49][32];
    __shared__ float bnS[3][32], bnB[3][32];

    const int t = threadIdx.x, lane = t & 31, w = t >> 5, blk = blockIdx.x;

    // ---- init: zero padded bitmaps (borders stay 0), load/pack weights ----
    ((unsigned*)X1p)[t] = 0u;          // 256 words exactly
    if (t < 81) ((unsigned*)X2p)[t] = 0u;
    for (int i = t; i < 288; i += NT) ws[i] = w0[i];
    for (int task = w; task < 576; task += NW) {     // lane = input channel
        const float* wsrc = (task < 288) ? w1 : w2;
        int r = (task < 288) ? task : task - 288;
        int o = r / 9, tap = r % 9;
        unsigned bal = __ballot_sync(FULL, wsrc[o*288 + lane*9 + tap] > 0.f);
        if (lane == 0) ((task < 288) ? Wb1 : Wb2)[r] = bal;
    }
    __syncthreads();

    // =================== P1: conv0 (Cin=1, pad=1) + 2x2 pool + stats ========
    {
        float wr[9];
#pragma unroll
        for (int k = 0; k < 9; k++) wr[k] = ws[lane*9 + k];
        float s1 = 0.f, q1 = 0.f;
        for (int img = blk; img < B; img += GRID) {
            __syncthreads();           // previous image's compute done
            const float* xb = x + img*784;
            for (int i = t; i < 784; i += NT) {
                int r = i / 28;
                xs[r + 1][i - r*28 + 1] = xb[i];
            }
            __syncthreads();
            // flat strip-level distribution: 98 strips, 13-vs-12 per warp
            for (int u = w; u < 98; u += NW) {
                int py = u / 7;
                int j2 = u - py*7;
                float acc[8];          // [half*4 + dy*2 + dx]
#pragma unroll
                for (int k = 0; k < 8; k++) acc[k] = 0.f;
#pragma unroll
                for (int r = 0; r < 4; r++) {   // row-streaming: low live set
                    float4 a4 = *reinterpret_cast<const float4*>(&xs[2*py + r][4*j2]);
                    float2 b2 = *reinterpret_cast<const float2*>(&xs[2*py + r][4*j2 + 4]);
                    float e[6] = {a4.x, a4.y, a4.z, a4.w, b2.x, b2.y};
#pragma unroll
                    for (int dy = 0; dy < 2; dy++) {
                        int ky = r - dy;
                        if (ky >= 0 && ky < 3) {
#pragma unroll
                            for (int half = 0; half < 2; half++)
#pragma unroll
                                for (int dx = 0; dx < 2; dx++) {
                                    float a = acc[half*4 + dy*2 + dx];
#pragma unroll
                                    for (int kx = 0; kx < 3; kx++)
                                        a = fmaf(wr[ky*3 + kx], e[2*half + dx + kx], a);
                                    acc[half*4 + dy*2 + dx] = a;
                                }
                        }
                    }
                }
                float m0 = fmaxf(fmaxf(acc[0], acc[1]), fmaxf(acc[2], acc[3]));
                float m1 = fmaxf(fmaxf(acc[4], acc[5]), fmaxf(acc[6], acc[7]));
                float* outp = d_t0 + (img*196 + py*14 + 2*j2)*32 + lane;
                outp[0]  = m0;
                outp[32] = m1;
                s1 += m0 + m1;
                q1 = fmaf(m0, m0, q1); q1 = fmaf(m1, m1, q1);
            }
        }
        __syncthreads();
        ss[w][lane] = s1; sq[w][lane] = q1;
        __syncthreads();
        if (t < 32) {
            float ts = 0.f, tq = 0.f;
#pragma unroll
            for (int j = 0; j < NW; j++) { ts += ss[j][t]; tq += sq[j][t]; }
            d_psA[0][blk*32 + t] = ts;
            d_pqA[0][blk*32 + t] = tq;
        }
    }
    gbarrier(0);
    // finalize BN0 (all blocks redundantly; fully coalesced 128B rows)
    {
        float fs = 0.f, fq = 0.f;
        for (int i = w; i < GRID; i += NW) {
            fs += ldcg_f(&d_psA[0][i*32 + lane]);
            fq += ldcg_f(&d_pqA[0][i*32 + lane]);
        }
        dsum[w][lane] = (double)fs; dqsum[w][lane] = (double)fq;
        __syncthreads();
        if (t < 32) {
            double s = 0.0, q = 0.0;
#pragma unroll
            for (int j = 0; j < NW; j++) { s += dsum[j][t]; q += dqsum[j][t]; }
            double n = (double)B * 196.0;
            double mean = s / n, var = q / n - mean * mean;
            double sc = (double)g0[t] / sqrt(var + 1e-5);
            bnS[0][t] = (float)sc;
            bnB[0][t] = (float)((double)b0[t] - mean * sc);
        }
        __syncthreads();
    }

    // =================== P2: pack X1 + p1 + binary conv1 + pool + stats =====
    {
        unsigned wb[9];
#pragma unroll
        for (int k = 0; k < 9; k++) wb[k] = Wb1[lane*9 + k];
        float sc = bnS[0][lane], bs = bnB[0][lane];
        float s2 = 0.f, q2 = 0.f;
        for (int img = blk; img < B; img += GRID) {
            const float* t0b = d_t0 + img*196*32 + lane;
            // ---- pack + p1, 2 pixels per iteration for MLP ----
            for (int j = w; j < 49; j += 2*NW) {
                int pyA = j / 7, pxA = j - 7*pyA;
                int jB = j + NW;
                bool two = jB < 49;                 // warp-uniform
                int pyB = jB / 7; if (!two) pyB = 0;
                int pxB = jB - 7*pyB; if (!two) pxB = 0;
                const float* qA = t0b + (pyA*28 + 2*pxA)*32;
                const float* qB = t0b + (pyB*28 + 2*pxB)*32;
                float a0 = qA[0],      a1 = qA[32];
                float a2 = qA[14*32],  a3 = qA[15*32];
                float c0 = 0.f, c1 = 0.f, c2 = 0.f, c3 = 0.f;
                if (two) { c0 = qB[0]; c1 = qB[32]; c2 = qB[14*32]; c3 = qB[15*32]; }
                float hA0 = fmaf(sc, a0, bs), hA1 = fmaf(sc, a1, bs);
                float hA2 = fmaf(sc, a2, bs), hA3 = fmaf(sc, a3, bs);
                unsigned bA0 = __ballot_sync(FULL, hA0 > 0.f);
                unsigned bA1 = __ballot_sync(FULL, hA1 > 0.f);
                unsigned bA2 = __ballot_sync(FULL, hA2 > 0.f);
                unsigned bA3 = __ballot_sync(FULL, hA3 > 0.f);
                unsigned mywA = (lane == 0) ? bA0 : (lane == 1) ? bA1
                              : (lane == 2) ? bA2 : bA3;
                if (lane < 4)
                    X1p[2*pyA + (lane>>1) + 1][2*pxA + (lane&1) + 1] = mywA;
                d_p1[(img*49 + j)*32 + lane] = fmaxf(fmaxf(hA0, hA1), fmaxf(hA2, hA3));
                if (two) {
                    float hB0 = fmaf(sc, c0, bs), hB1 = fmaf(sc, c1, bs);
                    float hB2 = fmaf(sc, c2, bs), hB3 = fmaf(sc, c3, bs);
                    unsigned bB0 = __ballot_sync(FULL, hB0 > 0.f);
                    unsigned bB1 = __ballot_sync(FULL, hB1 > 0.f);
                    unsigned bB2 = __ballot_sync(FULL, hB2 > 0.f);
                    unsigned bB3 = __ballot_sync(FULL, hB3 > 0.f);
                    unsigned mywB = (lane == 0) ? bB0 : (lane == 1) ? bB1
                                  : (lane == 2) ? bB2 : bB3;
                    if (lane < 4)
                        X1p[2*pyB + (lane>>1) + 1][2*pxB + (lane&1) + 1] = mywB;
                    d_p1[(img*49 + jB)*32 + lane] =
                        fmaxf(fmaxf(hB0, hB1), fmaxf(hB2, hB3));
                }
            }
            __syncthreads();
            // ---- binary conv + pool from smem bitmap ----
            {
                int py = w / 7, px = w - 7*(w/7);
                float* u1b = d_u1 + (img*49 + w)*32 + lane;
                for (int j = w; j < 49; j += NW) {
                    unsigned xw[4][4];
#pragma unroll
                    for (int r4 = 0; r4 < 4; r4++) {
                        const uint2* Xr = reinterpret_cast<const uint2*>(&X1p[2*py + r4][2*px]);
                        uint2 lo = Xr[0], hi = Xr[1];
                        xw[r4][0] = lo.x; xw[r4][1] = lo.y; xw[r4][2] = hi.x; xw[r4][3] = hi.y;
                    }
                    int vv[4];
#pragma unroll
                    for (int dy = 0; dy < 2; dy++)
#pragma unroll
                        for (int dx = 0; dx < 2; dx++) {
                            int sump = 0;
#pragma unroll
                            for (int ky = 0; ky < 3; ky++)
#pragma unroll
                                for (int kx = 0; kx < 3; kx++)
                                    sump += __popc(xw[dy+ky][dx+kx] ^ wb[ky*3+kx]);
                            vv[dy*2+dx] = 288 - 2*sump;
                        }
                    if (py == 0 || py == 6 || px == 0 || px == 6) {
                        // recompute border constants here (keeps regs low on hot path)
                        int Kc0 = 32 - 2*__popc(wb[0]);
                        int Kc1 = 32 - 2*__popc(wb[1]);
                        int Kc2 = 32 - 2*__popc(wb[2]);
                        int Kc3 = 32 - 2*__popc(wb[3]);
                        int Kc5 = 32 - 2*__popc(wb[5]);
                        int Kc6 = 32 - 2*__popc(wb[6]);
                        int Kc7 = 32 - 2*__popc(wb[7]);
                        int Kc8 = 32 - 2*__popc(wb[8]);
                        int Kt = Kc0 + Kc1 + Kc2, Kb = Kc6 + Kc7 + Kc8;
                        int Kl = Kc0 + Kc3 + Kc6, Kr = Kc2 + Kc5 + Kc8;
#pragma unroll
                        for (int dy = 0; dy < 2; dy++)
#pragma unroll
                            for (int dx = 0; dx < 2; dx++) {
                                bool top = (py == 0) && (dy == 0);
                                bool bot = (py == 6) && (dy == 1);
                                bool lef = (px == 0) && (dx == 0);
                                bool rig = (px == 6) && (dx == 1);
                                int corr = 0;
                                if (top) corr += Kt;
                                if (bot) corr += Kb;
                                if (lef) corr += Kl;
                                if (rig) corr += Kr;
                                if (top && lef) corr -= Kc0;
                                if (top && rig) corr -= Kc2;
                                if (bot && lef) corr -= Kc6;
                                if (bot && rig) corr -= Kc8;
                                vv[dy*2+dx] -= corr;
                            }
                    }
                    int m = max(max(vv[0], vv[1]), max(vv[2], vv[3]));
                    float fm = (float)m;
                    u1b[0] = fm;
                    u1b += NW*32;
                    s2 += fm; q2 = fmaf(fm, fm, q2);
                    px += 1; py += 1;
                    if (px >= 7) { px -= 7; py += 1; }
                }
            }
            __syncthreads();           // X1p reusable for next image
        }
        __syncthreads();
        ss[w][lane] = s2; sq[w][lane] = q2;
        __syncthreads();
        if (t < 32) {
            float ts = 0.f, tq = 0.f;
#pragma unroll
            for (int j = 0; j < NW; j++) { ts += ss[j][t]; tq += sq[j][t]; }
            d_psA[1][blk*32 + t] = ts;
            d_pqA[1][blk*32 + t] = tq;
        }
    }
    gbarrier(1);
    {
        float fs = 0.f, fq = 0.f;
        for (int i = w; i < GRID; i += NW) {
            fs += ldcg_f(&d_psA[1][i*32 + lane]);
            fq += ldcg_f(&d_pqA[1][i*32 + lane]);
        }
        dsum[w][lane] = (double)fs; dqsum[w][lane] = (double)fq;
        __syncthreads();
        if (t < 32) {
            double s = 0.0, q = 0.0;
#pragma unroll
            for (int j = 0; j < NW; j++) { s += dsum[j][t]; q += dqsum[j][t]; }
            double n = (double)B * 49.0;
            double mean = s / n, var = q / n - mean * mean;
            double sc = (double)g1[t] / sqrt(var + 1e-5);
            bnS[1][t] = (float)sc;
            bnB[1][t] = (float)((double)b1[t] - mean * sc);
        }
        __syncthreads();
    }

    // =================== P3: h1 + X2 + p2 + binary conv2 + stats ============
    {
        unsigned wb[9];
#pragma unroll
        for (int k = 0; k < 9; k++) wb[k] = Wb2[lane*9 + k];
        float sc = bnS[1][lane], bs = bnB[1][lane];
        float s3 = 0.f, q3 = 0.f;
        for (int img = blk; img < B; img += GRID) {
            // ---- h1 + X2 pack, 2 pixels per iteration ----
            for (int j = w; j < 49; j += 2*NW) {
                int jB = j + NW;
                bool two = jB < 49;                 // warp-uniform
                const float* u1a = d_u1 + (img*49 + j)*32 + lane;
                const float* p1a = d_p1 + (img*49 + j)*32 + lane;
                float uA = u1a[0], pA = p1a[0];
                float uB = 0.f, pB = 0.f;
                if (two) { uB = u1a[NW*32]; pB = p1a[NW*32]; }
                float hA = fmaf(sc, uA, bs) + pA;
                h1s[j][lane] = hA;
                unsigned balA = __ballot_sync(FULL, hA > 0.f);
                if (lane == 0) X2p[j/7 + 1][j%7 + 1] = balA;
                if (two) {
                    float hB = fmaf(sc, uB, bs) + pB;
                    h1s[jB][lane] = hB;
                    unsigned balB = __ballot_sync(FULL, hB > 0.f);
                    if (lane == 0) X2p[jB/7 + 1][jB%7 + 1] = balB;
                }
            }
            __syncthreads();
            for (int j = w; j < 9; j += NW) {
                int pyy = (j >= 6) ? 2 : (j >= 3 ? 1 : 0);
                int pxx = j - 3*pyy;
                int i0 = (2*pyy)*7 + 2*pxx;
                float m = fmaxf(fmaxf(h1s[i0][lane],   h1s[i0+1][lane]),
                                fmaxf(h1s[i0+7][lane], h1s[i0+8][lane]));
                d_p2[(img*9 + j)*32 + lane] = m;
                unsigned xw[4][4];
#pragma unroll
                for (int r4 = 0; r4 < 4; r4++)
#pragma unroll
                    for (int c4 = 0; c4 < 4; c4++)
                        xw[r4][c4] = X2p[2*pyy + r4][2*pxx + c4];
                int mm = -100000;
#pragma unroll
                for (int dy = 0; dy < 2; dy++)
#pragma unroll
                    for (int dx = 0; dx < 2; dx++) {
                        int sump = 0;
#pragma unroll
                        for (int ky = 0; ky < 3; ky++)
#pragma unroll
                            for (int kx = 0; kx < 3; kx++)
                                sump += __popc(xw[dy+ky][dx+kx] ^ wb[ky*3+kx]);
                        int v = 288 - 2*sump;
                        bool top = (pyy == 0) && (dy == 0);
                        bool lef = (pxx == 0) && (dx == 0);
                        if (top || lef) {
                            int Kc0 = 32 - 2*__popc(wb[0]);
                            int corr = 0;
                            if (top) corr += Kc0 + (32 - 2*__popc(wb[1]))
                                           + (32 - 2*__popc(wb[2]));
                            if (lef) corr += Kc0 + (32 - 2*__popc(wb[3]))
                                           + (32 - 2*__popc(wb[6]));
                            if (top && lef) corr -= Kc0;
                            v -= corr;
                        }
                        mm = max(mm, v);
                    }
                float fm = (float)mm;
                d_u2[(img*9 + j)*32 + lane] = fm;
                s3 += fm; q3 = fmaf(fm, fm, q3);
            }
            __syncthreads();
        }
        __syncthreads();
        ss[w][lane] = s3; sq[w][lane] = q3;
        __syncthreads();
        if (t < 32) {
            float ts = 0.f, tq = 0.f;
#pragma unroll
            for (int j = 0; j < NW; j++) { ts += ss[j][t]; tq += sq[j][t]; }
            d_psA[2][blk*32 + t] = ts;
            d_pqA[2][blk*32 + t] = tq;
        }
    }
    gbarrier(2);
    {
        float fs = 0.f, fq = 0.f;
        for (int i = w; i < GRID; i += NW) {
            fs += ldcg_f(&d_psA[2][i*32 + lane]);
            fq += ldcg_f(&d_pqA[2][i*32 + lane]);
        }
        dsum[w][lane] = (double)fs; dqsum[w][lane] = (double)fq;
        __syncthreads();
        if (t < 32) {
            double s = 0.0, q = 0.0;
#pragma unroll
            for (int j = 0; j < NW; j++) { s += dsum[j][t]; q += dqsum[j][t]; }
            double n = (double)B * 9.0;
            double mean = s / n, var = q / n - mean * mean;
            double sc = (double)g2[t] / sqrt(var + 1e-5);
            bnS[2][t] = (float)sc;
            bnB[2][t] = (float)((double)b2[t] - mean * sc);
        }
        __syncthreads();
    }

    // =================== P4: fused h2 = bn(u2)+p2, flatten, FC ==============
    {
        float sc = bnS[2][lane], bs = bnB[2][lane];
        int b = blk*NW + w;            // GRID*NW = 5920 >= B: at most one image/warp
        if (b < B) {
            float acc[10];
#pragma unroll
            for (int k = 0; k < 10; k++) acc[k] = 0.f;
#pragma unroll
            for (int ij = 0; ij < 9; ij++) {
                float h = fmaf(sc, ldcg_f(&d_u2[(b*9 + ij)*32 + lane]), bs)
                        + ldcg_f(&d_p2[(b*9 + ij)*32 + lane]);
#pragma unroll
                for (int k = 0; k < 10; k++)
                    acc[k] = fmaf(h, fw[k*288 + lane*9 + ij], acc[k]);
            }
#pragma unroll
            for (int k = 0; k < 10; k++) {
#pragma unroll
                for (int off = 16; off; off >>= 1)
                    acc[k] += __shfl_xor_sync(FULL, acc[k], off);
                if (lane == k) out[b*10 + k] = acc[k] + fb[k];
            }
        }
    }
}

// ---------------- launch -----------------------------------------------------
extern "C" void kernel_launch(void* const* d_in, const int* in_sizes, int n_in,
                              void* d_out, int out_size) {
    const float* x  = (const float*)d_in[0];
    const float* w0 = (const float*)d_in[1];
    const float* g0 = (const float*)d_in[2];
    const float* b0 = (const float*)d_in[3];
    const float* w1 = (const float*)d_in[4];
    const float* g1 = (const float*)d_in[5];
    const float* b1 = (const float*)d_in[6];
    const float* w2 = (const float*)d_in[7];
    const float* g2 = (const float*)d_in[8];
    const float* b2 = (const float*)d_in[9];
    const float* fw = (const float*)d_in[10];
    const float* fb = (const float*)d_in[11];
    float* out = (float*)d_out;

    mega<<<GRID, NT>>>(x, w0, g0, b0, w1, g1, b1, w2, g2, b2, fw, fb, out);
}

// round 17
// speedup vs baseline: 2.9490x; 1.0019x over previous
#include <cuda_runtime.h>
#include <math.h>

#define B 4096
#define GRID 740              // 5 CTAs per SM (148 SMs) -> co-resident wave
#define NT 256
#define NW 8
#define FULL 0xffffffffu

// ---------------- device scratch (no allocation allowed) -------------------
__device__ float d_t0[B*14*14*32];     // pooled conv0 output, channel-last
__device__ float d_p1[B*7*7*32];       // maxpool2(h0) shortcut
__device__ short d_u1[B*7*7*32];       // binary-conv1 pooled sums (exact ints)
__device__ float d_p2[B*3*3*32];       // maxpool2(h1)
__device__ short d_u2[B*3*3*32];       // binary-conv2 pooled sums
__device__ float d_psA[3][GRID*32];    // stats partials, coalesced: [blk][ch]
__device__ float d_pqA[3][GRID*32];
__device__ int   d_bar[4];             // monotonic barrier counters (zero-init)

__device__ __forceinline__ float ldcg_f(const float* p) {
    float v;
    asm volatile("ld.global.cg.f32 %0, [%1];" : "=f"(v) : "l"(p));
    return v;
}
__device__ __forceinline__ float ldcg_s16f(const short* p) {
    short v;
    asm volatile("ld.global.cg.s16 %0, [%1];" : "=h"(v) : "l"(p));
    return (float)v;
}

// monotonic global barrier: replay-safe, no reset needed
__device__ __forceinline__ void gbarrier(int k) {
    __syncthreads();
    if (threadIdx.x == 0) {
        __threadfence();
        int old = atomicAdd(&d_bar[k], 1);
        int target = (old / GRID + 1) * GRID;
        int v;
        do {
            asm volatile("ld.acquire.gpu.global.s32 %0, [%1];"
                         : "=r"(v) : "l"(&d_bar[k]));
        } while (v < target);
    }
    __syncthreads();
}

// ---------------- the one kernel --------------------------------------------
__global__ void __launch_bounds__(NT, 5) mega(
        const float* __restrict__ x,  const float* __restrict__ w0,
        const float* __restrict__ g0, const float* __restrict__ b0,
        const float* __restrict__ w1, const float* __restrict__ g1,
        const float* __restrict__ b1, const float* __restrict__ w2,
        const float* __restrict__ g2, const float* __restrict__ b2,
        const float* __restrict__ fw, const float* __restrict__ fb,
        float* __restrict__ out) {
    __shared__ __align__(16) float xs[30][32];       // zero-padded input image
    __shared__ float ws[288];          // conv0 weights
    __shared__ float ss[NW][33], sq[NW][33];
    __shared__ double dsum[NW][33], dqsum[NW][33];
    __shared__ __align__(16) unsigned X1p[16][16];   // padded sign bitmap (14x14)
    __shared__ __align__(16) unsigned X2p[9][9];     // padded sign bitmap (7x7)
    __shared__ unsigned Wb1[288], Wb2[288];
    __shared__ float h1s[49][32];
    __shared__ float bnS[3][32], bnB[3][32];

    const int t = threadIdx.x, lane = t & 31, w = t >> 5, blk = blockIdx.x;

    // ---- init: zero padded bitmaps (borders stay 0), load/pack weights ----
    ((unsigned*)X1p)[t] = 0u;          // 256 words exactly
    if (t < 81) ((unsigned*)X2p)[t] = 0u;
    for (int i = t; i < 288; i += NT) ws[i] = w0[i];
    for (int task = w; task < 576; task += NW) {     // lane = input channel
        const float* wsrc = (task < 288) ? w1 : w2;
        int r = (task < 288) ? task : task - 288;
        int o = r / 9, tap = r % 9;
        unsigned bal = __ballot_sync(FULL, wsrc[o*288 + lane*9 + tap] > 0.f);
        if (lane == 0) ((task < 288) ? Wb1 : Wb2)[r] = bal;
    }
    __syncthreads();

    // =================== P1: conv0 (Cin=1, pad=1) + 2x2 pool + stats ========
    {
        float wr[9];
#pragma unroll
        for (int k = 0; k < 9; k++) wr[k] = ws[lane*9 + k];
        float s1 = 0.f, q1 = 0.f;
        for (int img = blk; img < B; img += GRID) {
            __syncthreads();           // previous image's compute done
            const float* xb = x + img*784;
            for (int i = t; i < 784; i += NT) {
                int r = i / 28;
                xs[r + 1][i - r*28 + 1] = xb[i];
            }
            __syncthreads();
            // flat strip-level distribution: 98 strips
            for (int u = w; u < 98; u += NW) {
                int py = u / 7;
                int j2 = u - py*7;
                float acc[8];          // [half*4 + dy*2 + dx]
#pragma unroll
                for (int k = 0; k < 8; k++) acc[k] = 0.f;
#pragma unroll
                for (int r = 0; r < 4; r++) {   // row-streaming: low live set
                    float4 a4 = *reinterpret_cast<const float4*>(&xs[2*py + r][4*j2]);
                    float2 b2 = *reinterpret_cast<const float2*>(&xs[2*py + r][4*j2 + 4]);
                    float e[6] = {a4.x, a4.y, a4.z, a4.w, b2.x, b2.y};
#pragma unroll
                    for (int dy = 0; dy < 2; dy++) {
                        int ky = r - dy;
                        if (ky >= 0 && ky < 3) {
#pragma unroll
                            for (int half = 0; half < 2; half++)
#pragma unroll
                                for (int dx = 0; dx < 2; dx++) {
                                    float a = acc[half*4 + dy*2 + dx];
#pragma unroll
                                    for (int kx = 0; kx < 3; kx++)
                                        a = fmaf(wr[ky*3 + kx], e[2*half + dx + kx], a);
                                    acc[half*4 + dy*2 + dx] = a;
                                }
                        }
                    }
                }
                float m0 = fmaxf(fmaxf(acc[0], acc[1]), fmaxf(acc[2], acc[3]));
                float m1 = fmaxf(fmaxf(acc[4], acc[5]), fmaxf(acc[6], acc[7]));
                float* outp = d_t0 + (img*196 + py*14 + 2*j2)*32 + lane;
                outp[0]  = m0;
                outp[32] = m1;
                s1 += m0 + m1;
                q1 = fmaf(m0, m0, q1); q1 = fmaf(m1, m1, q1);
            }
        }
        __syncthreads();
        ss[w][lane] = s1; sq[w][lane] = q1;
        __syncthreads();
        if (t < 32) {
            float ts = 0.f, tq = 0.f;
#pragma unroll
            for (int j = 0; j < NW; j++) { ts += ss[j][t]; tq += sq[j][t]; }
            d_psA[0][blk*32 + t] = ts;
            d_pqA[0][blk*32 + t] = tq;
        }
    }
    gbarrier(0);
    // finalize BN0 (all blocks redundantly; fully coalesced 128B rows)
    {
        float fs = 0.f, fq = 0.f;
        for (int i = w; i < GRID; i += NW) {
            fs += ldcg_f(&d_psA[0][i*32 + lane]);
            fq += ldcg_f(&d_pqA[0][i*32 + lane]);
        }
        dsum[w][lane] = (double)fs; dqsum[w][lane] = (double)fq;
        __syncthreads();
        if (t < 32) {
            double s = 0.0, q = 0.0;
#pragma unroll
            for (int j = 0; j < NW; j++) { s += dsum[j][t]; q += dqsum[j][t]; }
            double n = (double)B * 196.0;
            double mean = s / n, var = q / n - mean * mean;
            double sc = (double)g0[t] / sqrt(var + 1e-5);
            bnS[0][t] = (float)sc;
            bnB[0][t] = (float)((double)b0[t] - mean * sc);
        }
        __syncthreads();
    }

    // =================== P2: pack X1 + p1 + binary conv1 + pool + stats =====
    {
        unsigned wb[9];
#pragma unroll
        for (int k = 0; k < 9; k++) wb[k] = Wb1[lane*9 + k];
        float sc = bnS[0][lane], bs = bnB[0][lane];
        float s2 = 0.f, q2 = 0.f;
        for (int img = blk; img < B; img += GRID) {
            const float* t0b = d_t0 + img*196*32 + lane;
            // ---- pack + p1: pairs cover pixels 0..47, no tail branch ----
            for (int j = w; j < 48; j += 2*NW) {
                int pyA = j / 7, pxA = j - 7*pyA;
                int jB = j + NW;
                int pyB = jB / 7, pxB = jB - 7*pyB;
                const float* qA = t0b + (pyA*28 + 2*pxA)*32;
                const float* qB = t0b + (pyB*28 + 2*pxB)*32;
                float a0 = qA[0],      a1 = qA[32];
                float a2 = qA[14*32],  a3 = qA[15*32];
                float c0 = qB[0],      c1 = qB[32];
                float c2 = qB[14*32],  c3 = qB[15*32];
                float hA0 = fmaf(sc, a0, bs), hA1 = fmaf(sc, a1, bs);
                float hA2 = fmaf(sc, a2, bs), hA3 = fmaf(sc, a3, bs);
                unsigned bA0 = __ballot_sync(FULL, hA0 > 0.f);
                unsigned bA1 = __ballot_sync(FULL, hA1 > 0.f);
                unsigned bA2 = __ballot_sync(FULL, hA2 > 0.f);
                unsigned bA3 = __ballot_sync(FULL, hA3 > 0.f);
                unsigned mywA = (lane == 0) ? bA0 : (lane == 1) ? bA1
                              : (lane == 2) ? bA2 : bA3;
                if (lane < 4)
                    X1p[2*pyA + (lane>>1) + 1][2*pxA + (lane&1) + 1] = mywA;
                d_p1[(img*49 + j)*32 + lane] = fmaxf(fmaxf(hA0, hA1), fmaxf(hA2, hA3));
                float hB0 = fmaf(sc, c0, bs), hB1 = fmaf(sc, c1, bs);
                float hB2 = fmaf(sc, c2, bs), hB3 = fmaf(sc, c3, bs);
                unsigned bB0 = __ballot_sync(FULL, hB0 > 0.f);
                unsigned bB1 = __ballot_sync(FULL, hB1 > 0.f);
                unsigned bB2 = __ballot_sync(FULL, hB2 > 0.f);
                unsigned bB3 = __ballot_sync(FULL, hB3 > 0.f);
                unsigned mywB = (lane == 0) ? bB0 : (lane == 1) ? bB1
                              : (lane == 2) ? bB2 : bB3;
                if (lane < 4)
                    X1p[2*pyB + (lane>>1) + 1][2*pxB + (lane&1) + 1] = mywB;
                d_p1[(img*49 + jB)*32 + lane] =
                    fmaxf(fmaxf(hB0, hB1), fmaxf(hB2, hB3));
            }
            if (w == 0) {              // pixel 48 = (6,6), one warp
                const float* qA = t0b + (6*28 + 12)*32;
                float a0 = qA[0],     a1 = qA[32];
                float a2 = qA[14*32], a3 = qA[15*32];
                float h0 = fmaf(sc, a0, bs), h1 = fmaf(sc, a1, bs);
                float h2 = fmaf(sc, a2, bs), h3 = fmaf(sc, a3, bs);
                unsigned b0_ = __ballot_sync(FULL, h0 > 0.f);
                unsigned b1_ = __ballot_sync(FULL, h1 > 0.f);
                unsigned b2_ = __ballot_sync(FULL, h2 > 0.f);
                unsigned b3_ = __ballot_sync(FULL, h3 > 0.f);
                unsigned myw = (lane == 0) ? b0_ : (lane == 1) ? b1_
                             : (lane == 2) ? b2_ : b3_;
                if (lane < 4) X1p[13 + (lane>>1)][13 + (lane&1)] = myw;
                d_p1[(img*49 + 48)*32 + lane] = fmaxf(fmaxf(h0, h1), fmaxf(h2, h3));
            }
            __syncthreads();
            // ---- binary conv + pool: INTERIOR pixels (py,px in 1..5), no corr
            for (int i = w; i < 25; i += NW) {
                int py = 1 + i/5, px = 1 + (i - 5*(i/5));
                unsigned xw[4][4];
#pragma unroll
                for (int r4 = 0; r4 < 4; r4++) {
                    const uint2* Xr = reinterpret_cast<const uint2*>(&X1p[2*py + r4][2*px]);
                    uint2 lo = Xr[0], hi = Xr[1];
                    xw[r4][0] = lo.x; xw[r4][1] = lo.y; xw[r4][2] = hi.x; xw[r4][3] = hi.y;
                }
                int vv[4];
#pragma unroll
                for (int dy = 0; dy < 2; dy++)
#pragma unroll
                    for (int dx = 0; dx < 2; dx++) {
                        int sump = 0;
#pragma unroll
                        for (int ky = 0; ky < 3; ky++)
#pragma unroll
                            for (int kx = 0; kx < 3; kx++)
                                sump += __popc(xw[dy+ky][dx+kx] ^ wb[ky*3+kx]);
                        vv[dy*2+dx] = 288 - 2*sump;
                    }
                int m = max(max(vv[0], vv[1]), max(vv[2], vv[3]));
                d_u1[(img*49 + py*7 + px)*32 + lane] = (short)m;
                float fm = (float)m;
                s2 += fm; q2 = fmaf(fm, fm, q2);
            }
            // ---- BORDER pixels (24), branchless mask-multiply corrections --
            for (int i = w; i < 24; i += NW) {
                int py, px;
                if (i < 7)       { py = 0;      px = i;     }
                else if (i < 14) { py = 6;      px = i - 7; }
                else if (i < 19) { py = i - 13; px = 0;     }
                else             { py = i - 18; px = 6;     }
                unsigned xw[4][4];
#pragma unroll
                for (int r4 = 0; r4 < 4; r4++) {
                    const uint2* Xr = reinterpret_cast<const uint2*>(&X1p[2*py + r4][2*px]);
                    uint2 lo = Xr[0], hi = Xr[1];
                    xw[r4][0] = lo.x; xw[r4][1] = lo.y; xw[r4][2] = hi.x; xw[r4][3] = hi.y;
                }
                int vv[4];
#pragma unroll
                for (int dy = 0; dy < 2; dy++)
#pragma unroll
                    for (int dx = 0; dx < 2; dx++) {
                        int sump = 0;
#pragma unroll
                        for (int ky = 0; ky < 3; ky++)
#pragma unroll
                            for (int kx = 0; kx < 3; kx++)
                                sump += __popc(xw[dy+ky][dx+kx] ^ wb[ky*3+kx]);
                        vv[dy*2+dx] = 288 - 2*sump;
                    }
                int Kc0 = 32 - 2*__popc(wb[0]);
                int Kc1 = 32 - 2*__popc(wb[1]);
                int Kc2 = 32 - 2*__popc(wb[2]);
                int Kc3 = 32 - 2*__popc(wb[3]);
                int Kc5 = 32 - 2*__popc(wb[5]);
                int Kc6 = 32 - 2*__popc(wb[6]);
                int Kc7 = 32 - 2*__popc(wb[7]);
                int Kc8 = 32 - 2*__popc(wb[8]);
                int Kt = Kc0 + Kc1 + Kc2, Kb = Kc6 + Kc7 + Kc8;
                int Kl = Kc0 + Kc3 + Kc6, Kr = Kc2 + Kc5 + Kc8;
                int topP = (py == 0), botP = (py == 6);
                int lefP = (px == 0), rigP = (px == 6);
                vv[0] -= topP*Kt + lefP*Kl - (topP & lefP)*Kc0;
                vv[1] -= topP*Kt + rigP*Kr - (topP & rigP)*Kc2;
                vv[2] -= botP*Kb + lefP*Kl - (botP & lefP)*Kc6;
                vv[3] -= botP*Kb + rigP*Kr - (botP & rigP)*Kc8;
                int m = max(max(vv[0], vv[1]), max(vv[2], vv[3]));
                d_u1[(img*49 + py*7 + px)*32 + lane] = (short)m;
                float fm = (float)m;
                s2 += fm; q2 = fmaf(fm, fm, q2);
            }
            __syncthreads();           // X1p reusable for next image
        }
        __syncthreads();
        ss[w][lane] = s2; sq[w][lane] = q2;
        __syncthreads();
        if (t < 32) {
            float ts = 0.f, tq = 0.f;
#pragma unroll
            for (int j = 0; j < NW; j++) { ts += ss[j][t]; tq += sq[j][t]; }
            d_psA[1][blk*32 + t] = ts;
            d_pqA[1][blk*32 + t] = tq;
        }
    }
    gbarrier(1);
    {
        float fs = 0.f, fq = 0.f;
        for (int i = w; i < GRID; i += NW) {
            fs += ldcg_f(&d_psA[1][i*32 + lane]);
            fq += ldcg_f(&d_pqA[1][i*32 + lane]);
        }
        dsum[w][lane] = (double)fs; dqsum[w][lane] = (double)fq;
        __syncthreads();
        if (t < 32) {
            double s = 0.0, q = 0.0;
#pragma unroll
            for (int j = 0; j < NW; j++) { s += dsum[j][t]; q += dqsum[j][t]; }
            double n = (double)B * 49.0;
            double mean = s / n, var = q / n - mean * mean;
            double sc = (double)g1[t] / sqrt(var + 1e-5);
            bnS[1][t] = (float)sc;
            bnB[1][t] = (float)((double)b1[t] - mean * sc);
        }
        __syncthreads();
    }

    // =================== P3: h1 + X2 + p2 + binary conv2 + stats ============
    {
        unsigned wb[9];
#pragma unroll
        for (int k = 0; k < 9; k++) wb[k] = Wb2[lane*9 + k];
        float sc = bnS[1][lane], bs = bnB[1][lane];
        float s3 = 0.f, q3 = 0.f;
        for (int img = blk; img < B; img += GRID) {
            // ---- h1 + X2 pack: pairs 0..47, tail pixel 48 by warp 0 ----
            for (int j = w; j < 48; j += 2*NW) {
                int jB = j + NW;
                const short* u1a = d_u1 + (img*49 + j)*32 + lane;
                const float* p1a = d_p1 + (img*49 + j)*32 + lane;
                float uA = (float)u1a[0],   pA = p1a[0];
                float uB = (float)u1a[NW*32], pB = p1a[NW*32];
                float hA = fmaf(sc, uA, bs) + pA;
                h1s[j][lane] = hA;
                unsigned balA = __ballot_sync(FULL, hA > 0.f);
                if (lane == 0) X2p[j/7 + 1][j%7 + 1] = balA;
                float hB = fmaf(sc, uB, bs) + pB;
                h1s[jB][lane] = hB;
                unsigned balB = __ballot_sync(FULL, hB > 0.f);
                if (lane == 0) X2p[jB/7 + 1][jB%7 + 1] = balB;
            }
            if (w == 0) {
                float uA = (float)d_u1[(img*49 + 48)*32 + lane];
                float pA = d_p1[(img*49 + 48)*32 + lane];
                float hA = fmaf(sc, uA, bs) + pA;
                h1s[48][lane] = hA;
                unsigned balA = __ballot_sync(FULL, hA > 0.f);
                if (lane == 0) X2p[7][7] = balA;
            }
            __syncthreads();
            for (int j = w; j < 9; j += NW) {
                int pyy = (j >= 6) ? 2 : (j >= 3 ? 1 : 0);
                int pxx = j - 3*pyy;
                int i0 = (2*pyy)*7 + 2*pxx;
                float m = fmaxf(fmaxf(h1s[i0][lane],   h1s[i0+1][lane]),
                                fmaxf(h1s[i0+7][lane], h1s[i0+8][lane]));
                d_p2[(img*9 + j)*32 + lane] = m;
                unsigned xw[4][4];
#pragma unroll
                for (int r4 = 0; r4 < 4; r4++)
#pragma unroll
                    for (int c4 = 0; c4 < 4; c4++)
                        xw[r4][c4] = X2p[2*pyy + r4][2*pxx + c4];
                int vv[4];
#pragma unroll
                for (int dy = 0; dy < 2; dy++)
#pragma unroll
                    for (int dx = 0; dx < 2; dx++) {
                        int sump = 0;
#pragma unroll
                        for (int ky = 0; ky < 3; ky++)
#pragma unroll
                            for (int kx = 0; kx < 3; kx++)
                                sump += __popc(xw[dy+ky][dx+kx] ^ wb[ky*3+kx]);
                        vv[dy*2+dx] = 288 - 2*sump;
                    }
                // branchless top/left corrections (only borders possible)
                int Kc0 = 32 - 2*__popc(wb[0]);
                int Kt = Kc0 + (32 - 2*__popc(wb[1])) + (32 - 2*__popc(wb[2]));
                int Kl = Kc0 + (32 - 2*__popc(wb[3])) + (32 - 2*__popc(wb[6]));
                int topP = (pyy == 0), lefP = (pxx == 0);
                vv[0] -= topP*Kt + lefP*Kl - (topP & lefP)*Kc0;
                vv[1] -= topP*Kt;
                vv[2] -= lefP*Kl;
                int mm = max(max(vv[0], vv[1]), max(vv[2], vv[3]));
                d_u2[(img*9 + j)*32 + lane] = (short)mm;
                float fm = (float)mm;
                s3 += fm; q3 = fmaf(fm, fm, q3);
            }
            __syncthreads();
        }
        __syncthreads();
        ss[w][lane] = s3; sq[w][lane] = q3;
        __syncthreads();
        if (t < 32) {
            float ts = 0.f, tq = 0.f;
#pragma unroll
            for (int j = 0; j < NW; j++) { ts += ss[j][t]; tq += sq[j][t]; }
            d_psA[2][blk*32 + t] = ts;
            d_pqA[2][blk*32 + t] = tq;
        }
    }
    gbarrier(2);
    {
        float fs = 0.f, fq = 0.f;
        for (int i = w; i < GRID; i += NW) {
            fs += ldcg_f(&d_psA[2][i*32 + lane]);
            fq += ldcg_f(&d_pqA[2][i*32 + lane]);
        }
        dsum[w][lane] = (double)fs; dqsum[w][lane] = (double)fq;
        __syncthreads();
        if (t < 32) {
            double s = 0.0, q = 0.0;
#pragma unroll
            for (int j = 0; j < NW; j++) { s += dsum[j][t]; q += dqsum[j][t]; }
            double n = (double)B * 9.0;
            double mean = s / n, var = q / n - mean * mean;
            double sc = (double)g2[t] / sqrt(var + 1e-5);
            bnS[2][t] = (float)sc;
            bnB[2][t] = (float)((double)b2[t] - mean * sc);
        }
        __syncthreads();
    }

    // =================== P4: fused h2 = bn(u2)+p2, flatten, FC ==============
    {
        float sc = bnS[2][lane], bs = bnB[2][lane];
        int b = blk*NW + w;            // GRID*NW = 5920 >= B: at most one image/warp
        if (b < B) {
            float acc[10];
#pragma unroll
            for (int k = 0; k < 10; k++) acc[k] = 0.f;
#pragma unroll
            for (int ij = 0; ij < 9; ij++) {
                float h = fmaf(sc, ldcg_s16f(&d_u2[(b*9 + ij)*32 + lane]), bs)
                        + ldcg_f(&d_p2[(b*9 + ij)*32 + lane]);
#pragma unroll
                for (int k = 0; k < 10; k++)
                    acc[k] = fmaf(h, fw[k*288 + lane*9 + ij], acc[k]);
            }
#pragma unroll
            for (int k = 0; k < 10; k++) {
#pragma unroll
                for (int off = 16; off; off >>= 1)
                    acc[k] += __shfl_xor_sync(FULL, acc[k], off);
                if (lane == k) out[b*10 + k] = acc[k] + fb[k];
            }
        }
    }
}

// ---------------- launch -----------------------------------------------------
extern "C" void kernel_launch(void* const* d_in, const int* in_sizes, int n_in,
                              void* d_out, int out_size) {
    const float* x  = (const float*)d_in[0];
    const float* w0 = (const float*)d_in[1];
    const float* g0 = (const float*)d_in[2];
    const float* b0 = (const float*)d_in[3];
    const float* w1 = (const float*)d_in[4];
    const float* g1 = (const float*)d_in[5];
    const float* b1 = (const float*)d_in[6];
    const float* w2 = (const float*)d_in[7];
    const float* g2 = (const float*)d_in[8];
    const float* b2 = (const float*)d_in[9];
    const float* fw = (const float*)d_in[10];
    const float* fb = (const float*)d_in[11];
    float* out = (float*)d_out;

    mega<<<GRID, NT>>>(x, w0, g0, b0, w1, g1, b1, w2, g2, b2, fw, fb, out);
}